// round 15
// baseline (speedup 1.0000x reference)
#include <cuda_runtime.h>
#include <cuda_fp16.h>
#include <cstdint>

#define BH_N    128
#define M_TOTAL 512
#define L_SPAN  2048
#define HD      128
#define KV_LEN  (M_TOTAL + L_SPAN)   // 2560
#define BM      64
#define BN      64
#define NKT     33
#define NPOS    32
#define THREADS 256                   // 8 warps: 2 row-groups x 4 column-quarters
#define SOFT_OFF 3.0f                 // fixed softmax offset; cancels in normalize

// ---------------- fp16 pre-converted global scratch ----------------
__device__ __half d_QH[(size_t)BH_N * M_TOTAL * HD];   // Q * 1/sqrt(128)
__device__ __half d_KH[(size_t)BH_N * KV_LEN * HD];    // K [b][k][d]
__device__ __half d_VT[(size_t)BH_N * HD * KV_LEN];    // V transposed [b][d][k]
__device__ __half d_PET[(size_t)L_SPAN * HD];          // PE transposed [l][d]

// ---------------- SMEM layout (half indices) ----------------
#define QS_H 0                       // 64 x 136
#define KS_H (QS_H + BM * 136)
#define VT_H (KS_H + BN * 136)       // 128 x 72 (VT[d][k])
#define PL_H (VT_H + HD * 72)        // 64 x 136 (PET rows)
#define PB_H (PL_H + BM * 136)       // 64 x 72 (probs)
#define RG_H (PB_H + BM * 72)        // ring fp32 from here
#define RG_F (RG_H / 2)
#define EX_F (RG_F + BM * 132)       // 4 x 64 float exchange (epilogue only)
#define SMEM_BYTES ((EX_F + 4 * BM) * 4)   // 114688

__device__ __forceinline__ void mma_f16(float* d, const uint32_t* a, const uint32_t* b) {
    asm volatile(
        "mma.sync.aligned.m16n8k16.row.col.f32.f16.f16.f32 "
        "{%0,%1,%2,%3}, {%4,%5,%6,%7}, {%8,%9}, {%0,%1,%2,%3};\n"
        : "+f"(d[0]), "+f"(d[1]), "+f"(d[2]), "+f"(d[3])
        : "r"(a[0]), "r"(a[1]), "r"(a[2]), "r"(a[3]), "r"(b[0]), "r"(b[1]));
}

#define LDSM4(r, addr) \
    asm volatile("ldmatrix.sync.aligned.m8n8.x4.shared.b16 {%0,%1,%2,%3}, [%4];" \
        : "=r"((r)[0]), "=r"((r)[1]), "=r"((r)[2]), "=r"((r)[3]) : "r"(addr))

#define CP16(dst_sh, src) \
    asm volatile("cp.async.cg.shared.global [%0], [%1], 16;\n" :: "r"(dst_sh), "l"(src))
#define CP_COMMIT() asm volatile("cp.async.commit_group;\n" ::: "memory")
#define CP_WAIT0()  asm volatile("cp.async.wait_group 0;\n" ::: "memory")
#define CP_WAIT1()  asm volatile("cp.async.wait_group 1;\n" ::: "memory")

// ---------------- pre-pass kernels ----------------
__global__ void cvtQ_kernel(const float* __restrict__ q) {
    size_t i = (size_t)blockIdx.x * 256 + threadIdx.x;
    const float s = 0.08838834764831845f;
    float4 v = reinterpret_cast<const float4*>(q)[i];
    __half2* o = reinterpret_cast<__half2*>(d_QH);
    o[2 * i]     = __floats2half2_rn(v.x * s, v.y * s);
    o[2 * i + 1] = __floats2half2_rn(v.z * s, v.w * s);
}
__global__ void cvtK_kernel(const float* __restrict__ k) {
    size_t i = (size_t)blockIdx.x * 256 + threadIdx.x;
    float4 v = reinterpret_cast<const float4*>(k)[i];
    __half2* o = reinterpret_cast<__half2*>(d_KH);
    o[2 * i]     = __floats2half2_rn(v.x, v.y);
    o[2 * i + 1] = __floats2half2_rn(v.z, v.w);
}
__global__ void transV_kernel(const float* __restrict__ V) {
    __shared__ float tile[32][33];
    int b = blockIdx.z, k0 = blockIdx.x * 32, d0 = blockIdx.y * 32;
    int tx = threadIdx.x, ty = threadIdx.y;
    const float* src = V + ((size_t)b * KV_LEN + k0) * HD + d0;
#pragma unroll
    for (int i = 0; i < 32; i += 8) tile[ty + i][tx] = src[(size_t)(ty + i) * HD + tx];
    __syncthreads();
    __half* dst = d_VT + ((size_t)b * HD + d0) * KV_LEN + k0;
#pragma unroll
    for (int i = 0; i < 32; i += 8)
        dst[(size_t)(ty + i) * KV_LEN + tx] = __float2half(tile[tx][ty + i]);
}
__global__ void transPE_kernel(const float* __restrict__ PE) {
    __shared__ float tile[32][33];
    int l0 = blockIdx.x * 32, d0 = blockIdx.y * 32;
    int tx = threadIdx.x, ty = threadIdx.y;
#pragma unroll
    for (int i = 0; i < 32; i += 8)
        tile[ty + i][tx] = PE[(size_t)(d0 + ty + i) * L_SPAN + l0 + tx];
    __syncthreads();
#pragma unroll
    for (int i = 0; i < 32; i += 8)
        d_PET[(size_t)(l0 + ty + i) * HD + d0 + tx] = __float2half(tile[tx][ty + i]);
}

// ---------------- main kernel ----------------
extern "C" __global__ void __launch_bounds__(THREADS, 2)
seq_attn_kernel(float* __restrict__ OUT)
{
    extern __shared__ __align__(16) char smraw[];
    __half*   smH = reinterpret_cast<__half*>(smraw);
    uint32_t* smW = reinterpret_cast<uint32_t*>(smraw);
    float*    smF = reinterpret_cast<float*>(smraw);

    const int tid  = threadIdx.x;
    const int warp = tid >> 5;
    const int lane = tid & 31;
    const int g    = lane >> 2;
    const int tg   = lane & 3;
    const int rg   = warp & 1;        // row group 0..1 (32 rows)
    const int qtr  = warp >> 1;       // column quarter 0..3
    const int m0   = blockIdx.x * BM;
    const int b    = blockIdx.y;

    const int kcb = qtr * 16;         // QK: 16 key cols
    const int dcb = qtr * 32;         // PV: 32 out dims

    const int c16 = tid & 15, r16 = tid >> 4;
    const int c8  = tid & 7,  r8  = tid >> 3;

    // ---- ldmatrix lane addresses ----
    const int lr  = lane & 15;
    const int lkh = (lane >> 4) * 8;
    const int bnr = ((lane >> 4) << 3) + (lane & 7);
    const int bkh = ((lane >> 3) & 1) * 8;

    const uint32_t aQ0 = (uint32_t)__cvta_generic_to_shared(
        smH + QS_H + (rg * 32 + lr) * 136 + lkh);
    const uint32_t aQ1 = aQ0 + 16 * 136 * 2;
    const uint32_t aK  = (uint32_t)__cvta_generic_to_shared(
        smH + KS_H + (kcb + bnr) * 136 + bkh);
    const uint32_t aP  = (uint32_t)__cvta_generic_to_shared(
        smH + PL_H + (kcb + bnr) * 136 + bkh);
    const uint32_t aV0 = (uint32_t)__cvta_generic_to_shared(
        smH + VT_H + (dcb + bnr) * 72 + bkh);
    const uint32_t aV1 = aV0 + 16 * 72 * 2;
    const uint32_t aB0 = (uint32_t)__cvta_generic_to_shared(
        smH + PB_H + (rg * 32 + lr) * 72 + lkh);
    const uint32_t aB1 = aB0 + 16 * 72 * 2;

    const __half* gK  = d_KH + ((size_t)b * KV_LEN + m0) * HD;
    const __half* gVT = d_VT + (size_t)b * HD * KV_LEN + m0;

    auto issueK = [&](int t) {
#pragma unroll
        for (int i = 0; i < 4; ++i) {
            const int r = r16 + 16 * i;
            uint32_t dst = (uint32_t)__cvta_generic_to_shared(smH + KS_H + r * 136 + 8 * c16);
            CP16(dst, gK + ((size_t)t * BN + r) * HD + 8 * c16);
        }
    };
    auto issueV = [&](int t) {
#pragma unroll
        for (int i = 0; i < 4; ++i) {
            const int d = r8 + 32 * i;
            uint32_t dst = (uint32_t)__cvta_generic_to_shared(smH + VT_H + d * 72 + 8 * c8);
            CP16(dst, gVT + (size_t)d * KV_LEN + t * BN + 8 * c8);
        }
    };
    auto issueP = [&](int t) {
#pragma unroll
        for (int i = 0; i < 4; ++i) {
            const int r = r16 + 16 * i;
            uint32_t dst = (uint32_t)__cvta_generic_to_shared(smH + PL_H + r * 136 + 8 * c16);
            CP16(dst, d_PET + ((size_t)t * BN + r) * HD + 8 * c16);
        }
    };

    // ---- prologue: group A = Q + K(0) + PL(0); group B = V(0) ----
    {
        const __half* gq = d_QH + ((size_t)b * M_TOTAL + m0) * HD;
#pragma unroll
        for (int i = 0; i < 4; ++i) {
            const int r = r16 + 16 * i;
            uint32_t dst = (uint32_t)__cvta_generic_to_shared(smH + QS_H + r * 136 + 8 * c16);
            CP16(dst, gq + (size_t)r * HD + 8 * c16);
        }
        issueK(0); issueP(0);
        CP_COMMIT();
        issueV(0);
        CP_COMMIT();
    }

    float O[2][4][4];
#pragma unroll
    for (int mt = 0; mt < 2; ++mt)
#pragma unroll
        for (int n = 0; n < 4; ++n)
#pragma unroll
            for (int e = 0; e < 4; ++e) O[mt][n][e] = 0.f;

    float l_run[2][2] = {{0.f, 0.f}, {0.f, 0.f}};   // [mt][h] sumexp (quarter-partial)

    uint32_t* Wpb = smW + (PB_H >> 1);

    for (int t = 0; t < NKT; ++t) {
        const bool do_pos = (t < NPOS);

        CP_WAIT1();        // K(t)/PL(t) landed; V(t) may still fly
        __syncthreads();   // S1: tile t K/PL visible CTA-wide

        // ---- S = Q @ K^T, Spos = Q @ PET (8 k16 steps via ldmatrix) ----
        float s[2][2][4], sp[2][2][4];
#pragma unroll
        for (int mt = 0; mt < 2; ++mt)
#pragma unroll
            for (int n = 0; n < 2; ++n)
#pragma unroll
                for (int e = 0; e < 4; ++e) { s[mt][n][e] = 0.f; sp[mt][n][e] = 0.f; }

#pragma unroll 4
        for (int ks = 0; ks < 8; ++ks) {
            const uint32_t off = ks * 32;
            uint32_t a0[4], a1[4], bk[4];
            LDSM4(a0, aQ0 + off);
            LDSM4(a1, aQ1 + off);
            LDSM4(bk, aK + off);
            mma_f16(s[0][0], a0, bk);     mma_f16(s[0][1], a0, bk + 2);
            mma_f16(s[1][0], a1, bk);     mma_f16(s[1][1], a1, bk + 2);
            if (do_pos) {
                uint32_t bp[4];
                LDSM4(bp, aP + off);
                mma_f16(sp[0][0], a0, bp); mma_f16(sp[0][1], a0, bp + 2);
                mma_f16(sp[1][0], a1, bp); mma_f16(sp[1][1], a1, bp + 2);
            }
        }

        // ---- Spos -> fp32 ring (row-group-private rows) ----
        if (do_pos) {
            const int base = (t & 1) * BN;
            float* rgb = smF + RG_F;
#pragma unroll
            for (int mt = 0; mt < 2; ++mt) {
                const int rr = rg * 32 + mt * 16 + g;
#pragma unroll
                for (int nt = 0; nt < 2; ++nt) {
                    const int c = kcb + nt * 8 + tg * 2;
                    rgb[rr * 132 + base + c]           = sp[mt][nt][0];
                    rgb[rr * 132 + base + c + 1]       = sp[mt][nt][1];
                    rgb[(rr + 8) * 132 + base + c]     = sp[mt][nt][2];
                    rgb[(rr + 8) * 132 + base + c + 1] = sp[mt][nt][3];
                }
            }
        }
        __syncthreads();   // S2: ALL warps done reading K/PL (and ring visible)
                           // -> safe to overwrite via prefetch below

        // ---- prefetch K/P for t+1 (own commit group) ----
        if (t + 1 < NKT) {
            issueK(t + 1);
            if (t + 1 < NPOS) issueP(t + 1);
            CP_COMMIT();
        }

        // ---- add pos logit, mask, fixed-offset exp, accumulate sum ----
        {
            const float* rgb = smF + RG_F;
#pragma unroll
            for (int mt = 0; mt < 2; ++mt) {
                float ps0 = 0.f, ps1 = 0.f;
#pragma unroll
                for (int nt = 0; nt < 2; ++nt) {
#pragma unroll
                    for (int e = 0; e < 4; ++e) {
                        const int j = kcb + nt * 8 + tg * 2 + (e & 1);
                        const int r = rg * 32 + mt * 16 + g + ((e < 2) ? 0 : 8);
                        const int l = t * BN + j - r;
                        float v;
                        if (l >= 0 && l < L_SPAN)
                            v = __expf(s[mt][nt][e] + rgb[r * 132 + (l & 127)] - SOFT_OFF);
                        else
                            v = 0.f;
                        s[mt][nt][e] = v;
                    }
                    ps0 += s[mt][nt][0] + s[mt][nt][1];
                    ps1 += s[mt][nt][2] + s[mt][nt][3];
                }
                l_run[mt][0] += ps0;
                l_run[mt][1] += ps1;
            }
        }

        // ---- probs -> PB (half2; row-group-private rows) ----
#pragma unroll
        for (int mt = 0; mt < 2; ++mt) {
            const int rr = rg * 32 + mt * 16 + g;
#pragma unroll
            for (int nt = 0; nt < 2; ++nt) {
                const int wi = qtr * 8 + nt * 4 + tg;
                __half2 h0 = __floats2half2_rn(s[mt][nt][0], s[mt][nt][1]);
                __half2 h1 = __floats2half2_rn(s[mt][nt][2], s[mt][nt][3]);
                Wpb[rr * 36 + wi]       = *reinterpret_cast<uint32_t*>(&h0);
                Wpb[(rr + 8) * 36 + wi] = *reinterpret_cast<uint32_t*>(&h1);
            }
        }

        // V(t) must have landed in EVERY thread (only K/P(t+1) may remain pending),
        // and a FULL barrier makes all threads' V cp.asyncs visible CTA-wide.
        if (t + 1 < NKT) CP_WAIT1(); else CP_WAIT0();
        __syncthreads();   // S4: probs + V(t) visible CTA-wide

        // ---- O += P @ V (4 k16 steps via ldmatrix) ----
#pragma unroll
        for (int ks = 0; ks < 4; ++ks) {
            const uint32_t off = ks * 32;
            uint32_t a0[4], a1[4], bv0[4], bv1[4];
            LDSM4(a0, aB0 + off);
            LDSM4(a1, aB1 + off);
            LDSM4(bv0, aV0 + off);
            LDSM4(bv1, aV1 + off);
            mma_f16(O[0][0], a0, bv0); mma_f16(O[0][1], a0, bv0 + 2);
            mma_f16(O[0][2], a0, bv1); mma_f16(O[0][3], a0, bv1 + 2);
            mma_f16(O[1][0], a1, bv0); mma_f16(O[1][1], a1, bv0 + 2);
            mma_f16(O[1][2], a1, bv1); mma_f16(O[1][3], a1, bv1 + 2);
        }
        __syncthreads();   // S5: V/PB buffers free CTA-wide

        if (t + 1 < NKT) { issueV(t + 1); CP_COMMIT(); }
    }

    // ---- epilogue: quarter-sum reduction, normalize, store ----
#pragma unroll
    for (int mt = 0; mt < 2; ++mt)
#pragma unroll
        for (int h = 0; h < 2; ++h) {
            l_run[mt][h] += __shfl_xor_sync(0xffffffffu, l_run[mt][h], 1);
            l_run[mt][h] += __shfl_xor_sync(0xffffffffu, l_run[mt][h], 2);
        }
    float* ex = smF + EX_F;
    if (tg == 0) {
#pragma unroll
        for (int mt = 0; mt < 2; ++mt)
#pragma unroll
            for (int h = 0; h < 2; ++h)
                ex[qtr * BM + rg * 32 + mt * 16 + h * 8 + g] = l_run[mt][h];
    }
    __syncthreads();
    float inv[2][2];
#pragma unroll
    for (int mt = 0; mt < 2; ++mt)
#pragma unroll
        for (int h = 0; h < 2; ++h) {
            const int row = rg * 32 + mt * 16 + h * 8 + g;
            float tsum = 0.f;
#pragma unroll
            for (int qq = 0; qq < 4; ++qq) tsum += ex[qq * BM + row];
            inv[mt][h] = 1.f / tsum;
        }

    float* go = OUT + ((size_t)b * M_TOTAL + m0) * HD;
#pragma unroll
    for (int mt = 0; mt < 2; ++mt) {
        const int rr = rg * 32 + mt * 16 + g;
#pragma unroll
        for (int nt8 = 0; nt8 < 4; ++nt8) {
            const int c = dcb + nt8 * 8 + tg * 2;
            *reinterpret_cast<float2*>(go + rr * HD + c) =
                make_float2(O[mt][nt8][0] * inv[mt][0], O[mt][nt8][1] * inv[mt][0]);
            *reinterpret_cast<float2*>(go + (rr + 8) * HD + c) =
                make_float2(O[mt][nt8][2] * inv[mt][1], O[mt][nt8][3] * inv[mt][1]);
        }
    }
}

extern "C" void kernel_launch(void* const* d_in, const int* in_sizes, int n_in,
                              void* d_out, int out_size) {
    const float* q  = (const float*)d_in[0];
    const float* k  = (const float*)d_in[1];
    const float* v  = (const float*)d_in[2];
    const float* pe = (const float*)d_in[3];
    float* out = (float*)d_out;

    cvtQ_kernel<<<(BH_N * M_TOTAL * HD / 4) / 256, 256>>>(q);
    cvtK_kernel<<<(size_t)(BH_N * KV_LEN * HD / 4) / 256, 256>>>(k);
    {
        dim3 gt(KV_LEN / 32, HD / 32, BH_N);
        transV_kernel<<<gt, dim3(32, 8)>>>(v);
    }
    {
        dim3 gp(L_SPAN / 32, HD / 32);
        transPE_kernel<<<gp, dim3(32, 8)>>>(pe);
    }

    cudaFuncSetAttribute(seq_attn_kernel,
                         cudaFuncAttributeMaxDynamicSharedMemorySize, SMEM_BYTES);
    dim3 grid(M_TOTAL / BM, BH_N);
    seq_attn_kernel<<<grid, THREADS, SMEM_BYTES>>>(out);
}

// round 16
// speedup vs baseline: 1.0186x; 1.0186x over previous
#include <cuda_runtime.h>
#include <cuda_fp16.h>
#include <cstdint>

#define BH_N    128
#define M_TOTAL 512
#define L_SPAN  2048
#define HD      128
#define KV_LEN  (M_TOTAL + L_SPAN)   // 2560
#define BM      64
#define BN      64
#define NKT     33
#define NPOS    32
#define THREADS 256                   // 8 warps: 2 row-groups x 4 column-quarters
#define SOFT_OFF 3.0f                 // fixed softmax offset; cancels in normalize

// ---------------- fp16 pre-converted global scratch ----------------
__device__ __half d_QH[(size_t)BH_N * M_TOTAL * HD];   // Q * 1/sqrt(128)
__device__ __half d_KH[(size_t)BH_N * KV_LEN * HD];    // K [b][k][d]
__device__ __half d_VT[(size_t)BH_N * HD * KV_LEN];    // V transposed [b][d][k]
__device__ __half d_PET[(size_t)L_SPAN * HD];          // PE transposed [l][d]

// ---------------- SMEM layout (half indices) ----------------
#define QS_H 0                       // 64 x 136
#define KS_H (QS_H + BM * 136)
#define VT_H (KS_H + BN * 136)       // 128 x 72 (VT[d][k])
#define PL_H (VT_H + HD * 72)        // 64 x 136 (PET rows)
#define PB_H (PL_H + BM * 136)       // 64 x 72 (probs)
#define RG_H (PB_H + BM * 72)        // ring fp32 from here
#define RG_F (RG_H / 2)
#define EX_F (RG_F + BM * 132)       // 4 x 64 float exchange (epilogue only)
#define SMEM_BYTES ((EX_F + 4 * BM) * 4)   // 114688

__device__ __forceinline__ void mma_f16(float* d, const uint32_t* a, const uint32_t* b) {
    asm volatile(
        "mma.sync.aligned.m16n8k16.row.col.f32.f16.f16.f32 "
        "{%0,%1,%2,%3}, {%4,%5,%6,%7}, {%8,%9}, {%0,%1,%2,%3};\n"
        : "+f"(d[0]), "+f"(d[1]), "+f"(d[2]), "+f"(d[3])
        : "r"(a[0]), "r"(a[1]), "r"(a[2]), "r"(a[3]), "r"(b[0]), "r"(b[1]));
}

#define LDSM4(r, addr) \
    asm volatile("ldmatrix.sync.aligned.m8n8.x4.shared.b16 {%0,%1,%2,%3}, [%4];" \
        : "=r"((r)[0]), "=r"((r)[1]), "=r"((r)[2]), "=r"((r)[3]) : "r"(addr))

#define CP16(dst_sh, src) \
    asm volatile("cp.async.cg.shared.global [%0], [%1], 16;\n" :: "r"(dst_sh), "l"(src))
#define CP_COMMIT() asm volatile("cp.async.commit_group;\n" ::: "memory")
#define CP_WAIT0()  asm volatile("cp.async.wait_group 0;\n" ::: "memory")
#define CP_WAIT1()  asm volatile("cp.async.wait_group 1;\n" ::: "memory")

// ---------------- pre-pass 1: Q and K fp32 -> fp16 (merged) ----------------
#define QBLKS ((BH_N * M_TOTAL * HD / 4) / 256)                 // 8192
#define KBLKS (((size_t)BH_N * KV_LEN * HD / 4) / 256)          // 40960
__global__ void cvtQK_kernel(const float* __restrict__ q, const float* __restrict__ k) {
    if (blockIdx.x < QBLKS) {
        size_t i = (size_t)blockIdx.x * 256 + threadIdx.x;
        const float s = 0.08838834764831845f;
        float4 v = reinterpret_cast<const float4*>(q)[i];
        __half2* o = reinterpret_cast<__half2*>(d_QH);
        o[2 * i]     = __floats2half2_rn(v.x * s, v.y * s);
        o[2 * i + 1] = __floats2half2_rn(v.z * s, v.w * s);
    } else {
        size_t i = (size_t)(blockIdx.x - QBLKS) * 256 + threadIdx.x;
        float4 v = reinterpret_cast<const float4*>(k)[i];
        __half2* o = reinterpret_cast<__half2*>(d_KH);
        o[2 * i]     = __floats2half2_rn(v.x, v.y);
        o[2 * i + 1] = __floats2half2_rn(v.z, v.w);
    }
}

// ---------------- pre-pass 2: V transpose + PE transpose (merged) ----------------
// grid (40, 4, 129): z<128 -> V batch z (64k x 32d tiles); z==128 -> PE (x<64 l-tiles... x covers 40; PE handled with x remapped)
// To cover PE's 64 l-tiles with grid.x=64 we set grid.x=64 and guard V at x>=40.
__global__ void transVPE_kernel(const float* __restrict__ V, const float* __restrict__ PE) {
    const int tx = threadIdx.x, ty = threadIdx.y;
    if (blockIdx.z < BH_N) {
        if (blockIdx.x >= KV_LEN / 64) return;
        __shared__ float tile[64][33];
        const int b = blockIdx.z, k0 = blockIdx.x * 64, d0 = blockIdx.y * 32;
        const float* src = V + ((size_t)b * KV_LEN + k0) * HD + d0;
        const int lin = ty * 32 + tx;
#pragma unroll
        for (int i = 0; i < 8; ++i) {
            const int idx = i * 256 + lin;
            const int row = idx >> 5, col = idx & 31;
            tile[row][col] = src[(size_t)row * HD + col];
        }
        __syncthreads();
        // write: for each d, warp writes 32 half2 = 128B contiguous
        __half2* dst2 = reinterpret_cast<__half2*>(
            d_VT + ((size_t)b * HD + d0) * KV_LEN + k0);
#pragma unroll
        for (int i = 0; i < 4; ++i) {
            const int d = ty + 8 * i;
            dst2[(size_t)d * (KV_LEN / 2) + tx] =
                __floats2half2_rn(tile[2 * tx][d], tile[2 * tx + 1][d]);
        }
    } else {
        // PE: [HD][L_SPAN] -> PET [L_SPAN][HD]; 32l x 32d tiles; grid.x covers 64 l-tiles
        __shared__ float tile[32][33];
        const int l0 = blockIdx.x * 32, d0 = blockIdx.y * 32;
#pragma unroll
        for (int i = 0; i < 32; i += 8)
            tile[ty + i][tx] = PE[(size_t)(d0 + ty + i) * L_SPAN + l0 + tx];
        __syncthreads();
#pragma unroll
        for (int i = 0; i < 32; i += 8)
            d_PET[(size_t)(l0 + ty + i) * HD + d0 + tx] = __float2half(tile[tx][ty + i]);
    }
}

// ---------------- main kernel (identical to the passing R13) ----------------
extern "C" __global__ void __launch_bounds__(THREADS, 2)
seq_attn_kernel(float* __restrict__ OUT)
{
    extern __shared__ __align__(16) char smraw[];
    __half*   smH = reinterpret_cast<__half*>(smraw);
    uint32_t* smW = reinterpret_cast<uint32_t*>(smraw);
    float*    smF = reinterpret_cast<float*>(smraw);

    const int tid  = threadIdx.x;
    const int warp = tid >> 5;
    const int lane = tid & 31;
    const int g    = lane >> 2;
    const int tg   = lane & 3;
    const int rg   = warp & 1;        // row group 0..1 (32 rows)
    const int qtr  = warp >> 1;       // column quarter 0..3
    const int m0   = blockIdx.x * BM;
    const int b    = blockIdx.y;

    const int kcb = qtr * 16;         // QK: 16 key cols
    const int dcb = qtr * 32;         // PV: 32 out dims

    const int c16 = tid & 15, r16 = tid >> 4;
    const int c8  = tid & 7,  r8  = tid >> 3;

    // ---- ldmatrix lane addresses ----
    const int lr  = lane & 15;
    const int lkh = (lane >> 4) * 8;
    const int bnr = ((lane >> 4) << 3) + (lane & 7);
    const int bkh = ((lane >> 3) & 1) * 8;

    const uint32_t aQ0 = (uint32_t)__cvta_generic_to_shared(
        smH + QS_H + (rg * 32 + lr) * 136 + lkh);
    const uint32_t aQ1 = aQ0 + 16 * 136 * 2;
    const uint32_t aK  = (uint32_t)__cvta_generic_to_shared(
        smH + KS_H + (kcb + bnr) * 136 + bkh);
    const uint32_t aP  = (uint32_t)__cvta_generic_to_shared(
        smH + PL_H + (kcb + bnr) * 136 + bkh);
    const uint32_t aV0 = (uint32_t)__cvta_generic_to_shared(
        smH + VT_H + (dcb + bnr) * 72 + bkh);
    const uint32_t aV1 = aV0 + 16 * 72 * 2;
    const uint32_t aB0 = (uint32_t)__cvta_generic_to_shared(
        smH + PB_H + (rg * 32 + lr) * 72 + lkh);
    const uint32_t aB1 = aB0 + 16 * 72 * 2;

    const __half* gK  = d_KH + ((size_t)b * KV_LEN + m0) * HD;
    const __half* gVT = d_VT + (size_t)b * HD * KV_LEN + m0;

    auto issueK = [&](int t) {
#pragma unroll
        for (int i = 0; i < 4; ++i) {
            const int r = r16 + 16 * i;
            uint32_t dst = (uint32_t)__cvta_generic_to_shared(smH + KS_H + r * 136 + 8 * c16);
            CP16(dst, gK + ((size_t)t * BN + r) * HD + 8 * c16);
        }
    };
    auto issueV = [&](int t) {
#pragma unroll
        for (int i = 0; i < 4; ++i) {
            const int d = r8 + 32 * i;
            uint32_t dst = (uint32_t)__cvta_generic_to_shared(smH + VT_H + d * 72 + 8 * c8);
            CP16(dst, gVT + (size_t)d * KV_LEN + t * BN + 8 * c8);
        }
    };
    auto issueP = [&](int t) {
#pragma unroll
        for (int i = 0; i < 4; ++i) {
            const int r = r16 + 16 * i;
            uint32_t dst = (uint32_t)__cvta_generic_to_shared(smH + PL_H + r * 136 + 8 * c16);
            CP16(dst, d_PET + ((size_t)t * BN + r) * HD + 8 * c16);
        }
    };

    // ---- prologue: group A = Q + K(0) + PL(0); group B = V(0) ----
    {
        const __half* gq = d_QH + ((size_t)b * M_TOTAL + m0) * HD;
#pragma unroll
        for (int i = 0; i < 4; ++i) {
            const int r = r16 + 16 * i;
            uint32_t dst = (uint32_t)__cvta_generic_to_shared(smH + QS_H + r * 136 + 8 * c16);
            CP16(dst, gq + (size_t)r * HD + 8 * c16);
        }
        issueK(0); issueP(0);
        CP_COMMIT();
        issueV(0);
        CP_COMMIT();
    }

    float O[2][4][4];
#pragma unroll
    for (int mt = 0; mt < 2; ++mt)
#pragma unroll
        for (int n = 0; n < 4; ++n)
#pragma unroll
            for (int e = 0; e < 4; ++e) O[mt][n][e] = 0.f;

    float l_run[2][2] = {{0.f, 0.f}, {0.f, 0.f}};   // [mt][h] sumexp (quarter-partial)

    uint32_t* Wpb = smW + (PB_H >> 1);

    for (int t = 0; t < NKT; ++t) {
        const bool do_pos = (t < NPOS);

        CP_WAIT1();        // K(t)/PL(t) landed; V(t) may still fly
        __syncthreads();   // S1: tile t K/PL visible CTA-wide

        // ---- S = Q @ K^T, Spos = Q @ PET (8 k16 steps via ldmatrix) ----
        float s[2][2][4], sp[2][2][4];
#pragma unroll
        for (int mt = 0; mt < 2; ++mt)
#pragma unroll
            for (int n = 0; n < 2; ++n)
#pragma unroll
                for (int e = 0; e < 4; ++e) { s[mt][n][e] = 0.f; sp[mt][n][e] = 0.f; }

#pragma unroll 4
        for (int ks = 0; ks < 8; ++ks) {
            const uint32_t off = ks * 32;
            uint32_t a0[4], a1[4], bk[4];
            LDSM4(a0, aQ0 + off);
            LDSM4(a1, aQ1 + off);
            LDSM4(bk, aK + off);
            mma_f16(s[0][0], a0, bk);     mma_f16(s[0][1], a0, bk + 2);
            mma_f16(s[1][0], a1, bk);     mma_f16(s[1][1], a1, bk + 2);
            if (do_pos) {
                uint32_t bp[4];
                LDSM4(bp, aP + off);
                mma_f16(sp[0][0], a0, bp); mma_f16(sp[0][1], a0, bp + 2);
                mma_f16(sp[1][0], a1, bp); mma_f16(sp[1][1], a1, bp + 2);
            }
        }

        // ---- Spos -> fp32 ring (row-group-private rows) ----
        if (do_pos) {
            const int base = (t & 1) * BN;
            float* rgb = smF + RG_F;
#pragma unroll
            for (int mt = 0; mt < 2; ++mt) {
                const int rr = rg * 32 + mt * 16 + g;
#pragma unroll
                for (int nt = 0; nt < 2; ++nt) {
                    const int c = kcb + nt * 8 + tg * 2;
                    rgb[rr * 132 + base + c]           = sp[mt][nt][0];
                    rgb[rr * 132 + base + c + 1]       = sp[mt][nt][1];
                    rgb[(rr + 8) * 132 + base + c]     = sp[mt][nt][2];
                    rgb[(rr + 8) * 132 + base + c + 1] = sp[mt][nt][3];
                }
            }
        }
        __syncthreads();   // S2: ALL warps done reading K/PL -> safe to prefetch-overwrite

        // ---- prefetch K/P for t+1 (own commit group) ----
        if (t + 1 < NKT) {
            issueK(t + 1);
            if (t + 1 < NPOS) issueP(t + 1);
            CP_COMMIT();
        }

        // ---- add pos logit, mask, fixed-offset exp, accumulate sum ----
        {
            const float* rgb = smF + RG_F;
#pragma unroll
            for (int mt = 0; mt < 2; ++mt) {
                float ps0 = 0.f, ps1 = 0.f;
#pragma unroll
                for (int nt = 0; nt < 2; ++nt) {
#pragma unroll
                    for (int e = 0; e < 4; ++e) {
                        const int j = kcb + nt * 8 + tg * 2 + (e & 1);
                        const int r = rg * 32 + mt * 16 + g + ((e < 2) ? 0 : 8);
                        const int l = t * BN + j - r;
                        float v;
                        if (l >= 0 && l < L_SPAN)
                            v = __expf(s[mt][nt][e] + rgb[r * 132 + (l & 127)] - SOFT_OFF);
                        else
                            v = 0.f;
                        s[mt][nt][e] = v;
                    }
                    ps0 += s[mt][nt][0] + s[mt][nt][1];
                    ps1 += s[mt][nt][2] + s[mt][nt][3];
                }
                l_run[mt][0] += ps0;
                l_run[mt][1] += ps1;
            }
        }

        // ---- probs -> PB (half2; row-group-private rows) ----
#pragma unroll
        for (int mt = 0; mt < 2; ++mt) {
            const int rr = rg * 32 + mt * 16 + g;
#pragma unroll
            for (int nt = 0; nt < 2; ++nt) {
                const int wi = qtr * 8 + nt * 4 + tg;
                __half2 h0 = __floats2half2_rn(s[mt][nt][0], s[mt][nt][1]);
                __half2 h1 = __floats2half2_rn(s[mt][nt][2], s[mt][nt][3]);
                Wpb[rr * 36 + wi]       = *reinterpret_cast<uint32_t*>(&h0);
                Wpb[(rr + 8) * 36 + wi] = *reinterpret_cast<uint32_t*>(&h1);
            }
        }

        // V(t) must have landed in EVERY thread, and a FULL barrier
        // makes all threads' V cp.asyncs visible CTA-wide.
        if (t + 1 < NKT) CP_WAIT1(); else CP_WAIT0();
        __syncthreads();   // S4: probs + V(t) visible CTA-wide

        // ---- O += P @ V (4 k16 steps via ldmatrix) ----
#pragma unroll
        for (int ks = 0; ks < 4; ++ks) {
            const uint32_t off = ks * 32;
            uint32_t a0[4], a1[4], bv0[4], bv1[4];
            LDSM4(a0, aB0 + off);
            LDSM4(a1, aB1 + off);
            LDSM4(bv0, aV0 + off);
            LDSM4(bv1, aV1 + off);
            mma_f16(O[0][0], a0, bv0); mma_f16(O[0][1], a0, bv0 + 2);
            mma_f16(O[0][2], a0, bv1); mma_f16(O[0][3], a0, bv1 + 2);
            mma_f16(O[1][0], a1, bv0); mma_f16(O[1][1], a1, bv0 + 2);
            mma_f16(O[1][2], a1, bv1); mma_f16(O[1][3], a1, bv1 + 2);
        }
        __syncthreads();   // S5: V/PB buffers free CTA-wide

        if (t + 1 < NKT) { issueV(t + 1); CP_COMMIT(); }
    }

    // ---- epilogue: quarter-sum reduction, normalize, store ----
#pragma unroll
    for (int mt = 0; mt < 2; ++mt)
#pragma unroll
        for (int h = 0; h < 2; ++h) {
            l_run[mt][h] += __shfl_xor_sync(0xffffffffu, l_run[mt][h], 1);
            l_run[mt][h] += __shfl_xor_sync(0xffffffffu, l_run[mt][h], 2);
        }
    float* ex = smF + EX_F;
    if (tg == 0) {
#pragma unroll
        for (int mt = 0; mt < 2; ++mt)
#pragma unroll
            for (int h = 0; h < 2; ++h)
                ex[qtr * BM + rg * 32 + mt * 16 + h * 8 + g] = l_run[mt][h];
    }
    __syncthreads();
    float inv[2][2];
#pragma unroll
    for (int mt = 0; mt < 2; ++mt)
#pragma unroll
        for (int h = 0; h < 2; ++h) {
            const int row = rg * 32 + mt * 16 + h * 8 + g;
            float tsum = 0.f;
#pragma unroll
            for (int qq = 0; qq < 4; ++qq) tsum += ex[qq * BM + row];
            inv[mt][h] = 1.f / tsum;
        }

    float* go = OUT + ((size_t)b * M_TOTAL + m0) * HD;
#pragma unroll
    for (int mt = 0; mt < 2; ++mt) {
        const int rr = rg * 32 + mt * 16 + g;
#pragma unroll
        for (int nt8 = 0; nt8 < 4; ++nt8) {
            const int c = dcb + nt8 * 8 + tg * 2;
            *reinterpret_cast<float2*>(go + rr * HD + c) =
                make_float2(O[mt][nt8][0] * inv[mt][0], O[mt][nt8][1] * inv[mt][0]);
            *reinterpret_cast<float2*>(go + (rr + 8) * HD + c) =
                make_float2(O[mt][nt8][2] * inv[mt][1], O[mt][nt8][3] * inv[mt][1]);
        }
    }
}

extern "C" void kernel_launch(void* const* d_in, const int* in_sizes, int n_in,
                              void* d_out, int out_size) {
    const float* q  = (const float*)d_in[0];
    const float* k  = (const float*)d_in[1];
    const float* v  = (const float*)d_in[2];
    const float* pe = (const float*)d_in[3];
    float* out = (float*)d_out;

    cvtQK_kernel<<<QBLKS + (int)KBLKS, 256>>>(q, k);
    {
        dim3 gt(64, HD / 32, BH_N + 1);   // z<128: V (x<40 used); z==128: PE (x<64 used)
        transVPE_kernel<<<gt, dim3(32, 8)>>>(v, pe);
    }

    cudaFuncSetAttribute(seq_attn_kernel,
                         cudaFuncAttributeMaxDynamicSharedMemorySize, SMEM_BYTES);
    dim3 grid(M_TOTAL / BM, BH_N);
    seq_attn_kernel<<<grid, THREADS, SMEM_BYTES>>>(out);
}